// round 14
// baseline (speedup 1.0000x reference)
#include <cuda_runtime.h>
#include <math.h>

#define NN 50000
#define NE 400000
#define D 128
#define NBS 512
#define GEB 3125  // NE/128

// ---------------- scratch ---------------------------------------------------
__device__ float g_h0[NN * D];
__device__ float g_h1[NN * D];
__device__ float g_hUVBC[4 * NN * D];  // U,V,B,C results; later P,Q
__device__ float g_agg[NN * D];
__device__ float g_psum[NBS * D];
__device__ float g_psq[NBS * D];
__device__ float g_epsum[GEB * D];
__device__ float g_epsq[GEB * D];
__device__ float g_mean[D];
__device__ float g_rstd[D];
__device__ float g_emean[D];
__device__ float g_erstd[D];
__device__ float g_vmoy[D];
__device__ float g_WA[9 * D];  // folded [emb_e_w; b] @ A0
__device__ float g_wpack[245760];

// ---------------- helpers ---------------------------------------------------
__device__ __forceinline__ float f2tf(float x) {
    unsigned r;
    asm("cvt.rna.tf32.f32 %0, %1;" : "=r"(r) : "f"(x));
    return __uint_as_float(r);
}

__device__ __forceinline__ void cpa16(void* smem, const void* g, bool pred) {
    unsigned s = (unsigned)__cvta_generic_to_shared(smem);
    int sz = pred ? 16 : 0;
    asm volatile("cp.async.cg.shared.global [%0], [%1], 16, %2;" ::"r"(s), "l"(g), "r"(sz));
}
__device__ __forceinline__ void cpa_commit() { asm volatile("cp.async.commit_group;"); }
template <int N>
__device__ __forceinline__ void cpa_wait() { asm volatile("cp.async.wait_group %0;" ::"n"(N)); }

__device__ __forceinline__ void mma_tf32(float* d, const unsigned* a, const unsigned* b) {
    asm volatile(
        "mma.sync.aligned.m16n8k8.row.col.f32.tf32.tf32.f32 "
        "{%0,%1,%2,%3}, {%4,%5,%6,%7}, {%8,%9}, {%0,%1,%2,%3};"
        : "+f"(d[0]), "+f"(d[1]), "+f"(d[2]), "+f"(d[3])
        : "r"(a[0]), "r"(a[1]), "r"(a[2]), "r"(a[3]), "r"(b[0]), "r"(b[1]));
}

#define AS_STRIDE 20
#define BS_STRIDE 136

__device__ __forceinline__ void do_kt(const float* __restrict__ As, const float* __restrict__ Bs,
                                      float (&acc)[2][8][4], int warp_m, int warp_n, int r,
                                      int c) {
#pragma unroll
    for (int kk = 0; kk < 2; kk++) {
        unsigned afr[2][4], bfr[8][2];
#pragma unroll
        for (int mt = 0; mt < 2; mt++) {
            int row0 = warp_m * 32 + mt * 16;
            afr[mt][0] = __float_as_uint(As[(row0 + r) * AS_STRIDE + kk * 8 + c]);
            afr[mt][1] = __float_as_uint(As[(row0 + 8 + r) * AS_STRIDE + kk * 8 + c]);
            afr[mt][2] = __float_as_uint(As[(row0 + r) * AS_STRIDE + kk * 8 + c + 4]);
            afr[mt][3] = __float_as_uint(As[(row0 + 8 + r) * AS_STRIDE + kk * 8 + c + 4]);
        }
#pragma unroll
        for (int nt = 0; nt < 8; nt++) {
            int col0 = warp_n * 64 + nt * 8;
            bfr[nt][0] = __float_as_uint(Bs[(kk * 8 + c) * BS_STRIDE + col0 + r]);
            bfr[nt][1] = __float_as_uint(Bs[(kk * 8 + c + 4) * BS_STRIDE + col0 + r]);
        }
#pragma unroll
        for (int mt = 0; mt < 2; mt++)
#pragma unroll
            for (int nt = 0; nt < 8; nt++) mma_tf32(acc[mt][nt], afr[mt], bfr[nt]);
    }
}

// ---------------- scatter max helper -----------------------------------------
__device__ __forceinline__ void atomicMaxFloat(float* addr, float val) {
    if (!signbit(val))
        atomicMax(reinterpret_cast<int*>(addr), __float_as_int(val));
    else
        atomicMin(reinterpret_cast<unsigned int*>(addr), __float_as_uint(val));
}

// ---------------- weight packing --------------------------------------------
// l*81920 + {U:0,V:16384,B:32768,C:49152,Ae:65536}; W0:163840(3x16384); Wk:212992(2x16384)
__global__ void pack_weights(const float* __restrict__ U, const float* __restrict__ V,
                             const float* __restrict__ B, const float* __restrict__ C,
                             const float* __restrict__ A, const float* __restrict__ W0,
                             const float* __restrict__ Wk) {
    int i = blockIdx.x * 256 + threadIdx.x;
    if (i >= 245760) return;
    int c = i >> 14, r = i & 16383;
    float v;
    if (c < 10) {
        int l = c / 5, w = c % 5;
        const float* base = (w == 0) ? U : (w == 1) ? V : (w == 2) ? B : (w == 3) ? C : A;
        v = base[l * 16384 + r];
    } else if (c < 13) {
        v = W0[(c - 10) * 16384 + r];
    } else {
        v = Wk[(c - 13) * 16384 + r];
    }
    g_wpack[i] = f2tf(v);
}

// ---------------- fold edge-embed into A0: WA = [emb_e_w; b] @ A0 ------------
__global__ void fold_WA(const float* __restrict__ ew, const float* __restrict__ ebias) {
    int c = threadIdx.x;  // 128
    const float* A = g_wpack + 65536;  // tf32-rounded A (layer 0)
    for (int f = 0; f < 8; f++) {
        float acc = 0.f;
        for (int k = 0; k < 128; k++) acc = fmaf(ew[f * 128 + k], A[k * 128 + c], acc);
        g_WA[f * 128 + c] = acc;
    }
    float acc = 0.f;
    for (int k = 0; k < 128; k++) acc = fmaf(ebias[k], A[k * 128 + c], acc);
    g_WA[8 * 128 + c] = acc;
}

// ---------------- node embedding (outputs tf32-rounded) ----------------------
template <int F, int ROWS>
__global__ void embed_kernel(const float* __restrict__ X, const float* __restrict__ W,
                             const float* __restrict__ b, float* __restrict__ out, int M) {
    __shared__ float ws[F * D];
    __shared__ float xs[ROWS][F];
    int tid = threadIdx.x;  // 128
    for (int i = tid; i < F * D; i += 128) ws[i] = W[i];
    float bias = b[tid];
    int r0 = blockIdx.x * ROWS;
    for (int i = tid; i < ROWS * F; i += 128) {
        int r = i / F, f = i % F;
        xs[r][f] = (r0 + r < M) ? X[(size_t)(r0 + r) * F + f] : 0.f;
    }
    __syncthreads();
    for (int r = 0; r < ROWS; r++) {
        if (r0 + r >= M) break;
        float acc = bias;
#pragma unroll
        for (int f = 0; f < F; f++) acc = fmaf(xs[r][f], ws[f * D + tid], acc);
        out[(size_t)(r0 + r) * D + tid] = f2tf(acc);
    }
}

// ---------------- plain TF32 GEMM: C[M,128]=A[M,128]@W -----------------------
struct SmemGemm {
    float As[2][128 * AS_STRIDE];
    float Bs[2][16 * BS_STRIDE];
};

__global__ __launch_bounds__(256) void gemm_tf32(const float* __restrict__ A,
                                                 const float* __restrict__ Wbase, int wstride,
                                                 float* __restrict__ Cbase, long cstride, int M) {
    __shared__ SmemGemm sm;
    const float* W = Wbase + (size_t)blockIdx.y * wstride;
    float* Cgm = Cbase + (size_t)blockIdx.y * cstride;
    int tid = threadIdx.x;
    int wid = tid >> 5, lane = tid & 31;
    int warp_m = wid & 3, warp_n = wid >> 2;
    int r = lane >> 2, c = lane & 3;
    int m0 = blockIdx.x * 128;

    float acc[2][8][4];
#pragma unroll
    for (int mt = 0; mt < 2; mt++)
#pragma unroll
        for (int nt = 0; nt < 8; nt++)
#pragma unroll
            for (int j = 0; j < 4; j++) acc[mt][nt][j] = 0.f;

    auto loadA = [&](int buf, int kt) {
#pragma unroll
        for (int i = 0; i < 2; i++) {
            int f = tid + i * 256;
            int row = f >> 2, k4 = f & 3;
            bool p = (m0 + row) < M;
            const float* g = A + (size_t)(m0 + row) * D + kt * 16 + k4 * 4;
            cpa16(&sm.As[buf][row * AS_STRIDE + k4 * 4], p ? g : (const void*)W, p);
        }
    };
    auto loadB = [&](int buf, int kt) {
#pragma unroll
        for (int i = 0; i < 2; i++) {
            int f = tid + i * 256;
            int k = f >> 5, n4 = f & 31;
            cpa16(&sm.Bs[buf][k * BS_STRIDE + n4 * 4], W + (size_t)(kt * 16 + k) * D + n4 * 4,
                  true);
        }
    };

    loadA(0, 0); loadB(0, 0); cpa_commit();
    loadA(1, 1); loadB(1, 1); cpa_commit();
    for (int kt = 0; kt < 8; kt++) {
        int buf = kt & 1;
        if (kt + 1 < 8) cpa_wait<1>(); else cpa_wait<0>();
        __syncthreads();
        do_kt(sm.As[buf], sm.Bs[buf], acc, warp_m, warp_n, r, c);
        __syncthreads();
        if (kt + 2 < 8) { loadA(buf, kt + 2); loadB(buf, kt + 2); cpa_commit(); }
    }

    int c2 = c * 2;
#pragma unroll
    for (int nt = 0; nt < 8; nt++) {
        int col = warp_n * 64 + nt * 8 + c2;
#pragma unroll
        for (int mt = 0; mt < 2; mt++) {
            int row = m0 + warp_m * 32 + mt * 16 + r;
            if (row < M)
                *reinterpret_cast<float2*>(Cgm + (size_t)row * D + col) =
                    make_float2(acc[mt][nt][0], acc[mt][nt][1]);
            if (row + 8 < M)
                *reinterpret_cast<float2*>(Cgm + (size_t)(row + 8) * D + col) =
                    make_float2(acc[mt][nt][2], acc[mt][nt][3]);
        }
    }
}

// ---- l=0 edge kernel (rank-9): stats over t2 = e_in@WA + WA[8] + hB[dst] +
//      hC[src] (t2 NOT materialized); gate e0 = f2tf(ebias + e_in@We);
//      fused scatter-max agg[dst] max= hV[src]*sigmoid(e0).
//      Block = 128 edges, 256 threads: thread owns 2 columns x 32 edges.
__global__ __launch_bounds__(256) void edge_l0_fused(const float* __restrict__ e_in,
                                                     const float* __restrict__ ew,
                                                     const float* __restrict__ ebias,
                                                     const int* __restrict__ src,
                                                     const int* __restrict__ dst) {
    __shared__ float s_ein[128 * 8];
    __shared__ int s_src[128];
    __shared__ int s_dst[128];
    __shared__ float red[4 * 256];
    int tid = threadIdx.x;
    int m0 = blockIdx.x * 128;
    if (tid < 128) {
        s_src[tid] = src[m0 + tid];
        s_dst[tid] = dst[m0 + tid];
    }
    for (int i = tid; i < 1024; i += 256) s_ein[i] = e_in[(size_t)m0 * 8 + i];

    int cp = tid & 63;   // column pair
    int c0 = cp * 2;
    int eg = tid >> 6;   // edge group 0..3
    float wa[9][2], we[8][2], eb2[2];
#pragma unroll
    for (int f = 0; f < 9; f++) {
        wa[f][0] = g_WA[f * 128 + c0];
        wa[f][1] = g_WA[f * 128 + c0 + 1];
    }
#pragma unroll
    for (int f = 0; f < 8; f++) {
        we[f][0] = ew[f * 128 + c0];
        we[f][1] = ew[f * 128 + c0 + 1];
    }
    eb2[0] = ebias[c0];
    eb2[1] = ebias[c0 + 1];
    __syncthreads();

    const float* hV = g_hUVBC + (size_t)NN * D;
    const float* hB = g_hUVBC + 2 * (size_t)NN * D;
    const float* hC = g_hUVBC + 3 * (size_t)NN * D;
    float sa = 0.f, qa = 0.f, sb = 0.f, qb = 0.f;
    for (int it = 0; it < 32; it++) {
        int row = it * 4 + eg;
        const float* er = s_ein + row * 8;
        float ta = wa[8][0], tb = wa[8][1];
        float ea = eb2[0], eb_ = eb2[1];
#pragma unroll
        for (int f = 0; f < 8; f++) {
            float x = er[f];
            ta = fmaf(x, wa[f][0], ta);
            tb = fmaf(x, wa[f][1], tb);
            ea = fmaf(x, we[f][0], ea);
            eb_ = fmaf(x, we[f][1], eb_);
        }
        ea = f2tf(ea);
        eb_ = f2tf(eb_);
        int s = s_src[row], d = s_dst[row];
        float2 hb = *reinterpret_cast<const float2*>(hB + (size_t)d * D + c0);
        float2 hc = *reinterpret_cast<const float2*>(hC + (size_t)s * D + c0);
        float2 hv = *reinterpret_cast<const float2*>(hV + (size_t)s * D + c0);
        float va = ta + hb.x + hc.x;
        float vb = tb + hb.y + hc.y;
        sa += va; qa += va * va;
        sb += vb; qb += vb * vb;
        float wga = 1.f / (1.f + __expf(-ea));
        float wgb = 1.f / (1.f + __expf(-eb_));
        atomicMaxFloat(&g_agg[(size_t)d * D + c0], hv.x * wga);
        atomicMaxFloat(&g_agg[(size_t)d * D + c0 + 1], hv.y * wgb);
    }
    red[tid] = sa;
    red[256 + tid] = qa;
    red[512 + tid] = sb;
    red[768 + tid] = qb;
    __syncthreads();
    if (tid < 64) {
        float S0 = red[tid] + red[tid + 64] + red[tid + 128] + red[tid + 192];
        float Q0 = red[256 + tid] + red[256 + tid + 64] + red[256 + tid + 128] + red[256 + tid + 192];
        float S1 = red[512 + tid] + red[512 + tid + 64] + red[512 + tid + 128] + red[512 + tid + 192];
        float Q1 = red[768 + tid] + red[768 + tid + 64] + red[768 + tid + 128] + red[768 + tid + 192];
        g_epsum[blockIdx.x * D + tid * 2] = S0;
        g_epsq[blockIdx.x * D + tid * 2] = Q0;
        g_epsum[blockIdx.x * D + tid * 2 + 1] = S1;
        g_epsq[blockIdx.x * D + tid * 2 + 1] = Q1;
    }
}

// ---- l=1: fused edge-update + scatter-max, 1 elem/thread; BOTH e0 and t2
//      recomputed bit-identically (hB0/hC0 still live in slots 2/3: the l=1
//      node GEMM only overwrites slots 0/1).
__global__ void edge_update_scatter(const float* __restrict__ e_in, const float* __restrict__ ew,
                                    const float* __restrict__ ebias, const int* __restrict__ src,
                                    const int* __restrict__ dst) {
    int idx = blockIdx.x * blockDim.x + threadIdx.x;
    if (idx >= NE * D) return;
    int eidx = idx >> 7;
    int d = idx & 127;
    int s = __ldg(src + eidx);
    int t = __ldg(dst + eidx);
    const float* er = e_in + (size_t)eidx * 8;
    // t2 recompute: WA[8] + ascending-f fmaf chain (matches edge_l0_fused)
    float ta = __ldg(g_WA + 8 * 128 + d);
    float e0 = __ldg(ebias + d);
#pragma unroll
    for (int f = 0; f < 8; f++) {
        float x = __ldg(er + f);
        ta = fmaf(x, __ldg(g_WA + f * 128 + d), ta);
        e0 = fmaf(x, __ldg(ew + f * 128 + d), e0);
    }
    e0 = f2tf(e0);
    const float* hV = g_hUVBC + (size_t)NN * D;
    const float* hB = g_hUVBC + 2 * (size_t)NN * D;
    const float* hC = g_hUVBC + 3 * (size_t)NN * D;
    float va = ta + hB[(size_t)t * D + d] + hC[(size_t)s * D + d];
    float x = (va - g_emean[d]) * g_erstd[d];
    float e1 = f2tf(e0 + fmaxf(x, 0.f));
    float w = 1.f / (1.f + __expf(-e1));
    atomicMaxFloat(&g_agg[(size_t)t * D + d], hV[(size_t)s * D + d] * w);
}

// ---------------- fill agg with -inf (vectorized) ----------------------------
__global__ void fill_neginf_kernel() {
    int i = blockIdx.x * blockDim.x + threadIdx.x;
    float4 v = make_float4(__int_as_float(0xff800000), __int_as_float(0xff800000),
                           __int_as_float(0xff800000), __int_as_float(0xff800000));
    if (i < NN * D / 4) reinterpret_cast<float4*>(g_agg)[i] = v;
}

// ---------------- BN stats ---------------------------------------------------
__global__ void node_pre_stats() {
    int c = threadIdx.x;
    const float* hU = g_hUVBC;
    float s = 0.f, q = 0.f;
    for (int r = blockIdx.x; r < NN; r += gridDim.x) {
        float a = g_agg[(size_t)r * D + c];
        if (!isfinite(a)) a = 0.f;
        float v = hU[(size_t)r * D + c] + a;
        s += v;
        q += v * v;
    }
    g_psum[blockIdx.x * D + c] = s;
    g_psq[blockIdx.x * D + c] = q;
}

__global__ void finalize_stats(const float* __restrict__ psum, const float* __restrict__ psq,
                               int nb, float inv_count, float* __restrict__ omean,
                               float* __restrict__ orstd) {
    int c = threadIdx.x;
    double s = 0.0, q = 0.0;
    for (int i = 0; i < nb; i++) {
        s += (double)psum[i * D + c];
        q += (double)psq[i * D + c];
    }
    double m = s * (double)inv_count;
    double v = q * (double)inv_count - m * m;
    omean[c] = (float)m;
    orstd[c] = rsqrtf((float)v + 1e-5f);
}

__global__ void node_update(const float* __restrict__ h, float* __restrict__ hn) {
    int i = blockIdx.x * blockDim.x + threadIdx.x;
    if (i >= NN * D) return;
    int c = i & 127;
    const float* hU = g_hUVBC;
    float a = g_agg[i];
    if (!isfinite(a)) a = 0.f;
    float v = hU[i] + a;
    float x = (v - g_mean[c]) * g_rstd[c];
    hn[i] = f2tf(h[i] + fmaxf(x, 0.f));
}

// ---------------- moy + vmoy -------------------------------------------------
__global__ void moy_partial(const float* __restrict__ h) {
    int c = threadIdx.x;
    float s = 0.f;
    for (int r = blockIdx.x; r < NN; r += gridDim.x) s += h[(size_t)r * D + c];
    g_psum[blockIdx.x * D + c] = s;
}

__global__ void finalize_moy_vmoy(const float* __restrict__ W0_b) {
    __shared__ float moy_s[D];
    int c = threadIdx.x;
    double s = 0.0;
    for (int i = 0; i < NBS; i++) s += (double)g_psum[i * D + c];
    moy_s[c] = (float)(s / (double)NN);
    __syncthreads();
    float v = W0_b[c];
    const float* W0a = g_wpack + 163840;
#pragma unroll 4
    for (int k = 0; k < D; k++) v = fmaf(moy_s[k], W0a[k * D + c], v);
    g_vmoy[c] = v;
}

// ---------------- fused readout MLP ------------------------------------------
template <bool ROUND>
__device__ __forceinline__ void mlp_stage(float* __restrict__ X, float* __restrict__ Wb,
                                          const float* __restrict__ Wg,
                                          const float* __restrict__ bias, int tid, int warp_m,
                                          int warp_n, int r, int c) {
    float acc[2][8][4];
#pragma unroll
    for (int mt = 0; mt < 2; mt++)
#pragma unroll
        for (int nt = 0; nt < 8; nt++)
#pragma unroll
            for (int j = 0; j < 4; j++) acc[mt][nt][j] = 0.f;

    auto loadW = [&](int buf, int kt) {
#pragma unroll
        for (int i = 0; i < 2; i++) {
            int f = tid + i * 256;
            int k = f >> 5, n4 = f & 31;
            cpa16(&Wb[buf * (16 * BS_STRIDE) + k * BS_STRIDE + n4 * 4],
                  Wg + (size_t)(kt * 16 + k) * D + n4 * 4, true);
        }
    };
    loadW(0, 0); cpa_commit();
    loadW(1, 1); cpa_commit();
    for (int kt = 0; kt < 8; kt++) {
        int buf = kt & 1;
        if (kt + 1 < 8) cpa_wait<1>(); else cpa_wait<0>();
        __syncthreads();
        do_kt(X + kt * (128 * AS_STRIDE), Wb + buf * (16 * BS_STRIDE), acc, warp_m, warp_n, r, c);
        __syncthreads();
        if (kt + 2 < 8) { loadW(buf, kt + 2); cpa_commit(); }
    }
    int c2 = c * 2;
#pragma unroll
    for (int nt = 0; nt < 8; nt++) {
        int col = warp_n * 64 + nt * 8 + c2;
        float b0 = bias[col], b1 = bias[col + 1];
#pragma unroll
        for (int mt = 0; mt < 2; mt++) {
            int row = warp_m * 32 + mt * 16 + r;
            float v0 = fmaxf(acc[mt][nt][0] + b0, 0.f);
            float v1 = fmaxf(acc[mt][nt][1] + b1, 0.f);
            float v2 = fmaxf(acc[mt][nt][2] + b0, 0.f);
            float v3 = fmaxf(acc[mt][nt][3] + b1, 0.f);
            if (ROUND) { v0 = f2tf(v0); v1 = f2tf(v1); v2 = f2tf(v2); v3 = f2tf(v3); }
            X[(col >> 4) * (128 * AS_STRIDE) + row * AS_STRIDE + (col & 15)] = v0;
            X[(col >> 4) * (128 * AS_STRIDE) + (row + 8) * AS_STRIDE + (col & 15)] = v2;
            X[((col + 1) >> 4) * (128 * AS_STRIDE) + row * AS_STRIDE + ((col + 1) & 15)] = v1;
            X[((col + 1) >> 4) * (128 * AS_STRIDE) + (row + 8) * AS_STRIDE + ((col + 1) & 15)] = v3;
        }
    }
    __syncthreads();
}

__global__ __launch_bounds__(256) void readout_fused(const int* __restrict__ src,
                                                     const int* __restrict__ dst,
                                                     const float* __restrict__ Wk,
                                                     const float* __restrict__ Wk_b,
                                                     const float* __restrict__ wf,
                                                     const float* __restrict__ wfb,
                                                     float* __restrict__ out) {
    extern __shared__ float dyn[];
    float* X = dyn;                       // 8*128*20 = 20480
    float* Wb = dyn + 20480;              // 2*16*136 = 4352
    float* vmoy_s = Wb + 4352;            // 128
    float* wf_s = vmoy_s + 128;           // 128
    int* s_src = (int*)(wf_s + 128);      // 128
    int* s_dst = s_src + 128;             // 128
    int tid = threadIdx.x;
    int m0 = blockIdx.x * 128;
    if (tid < 128) {
        s_src[tid] = src[m0 + tid];
        s_dst[tid] = dst[m0 + tid];
        vmoy_s[tid] = g_vmoy[tid];
        wf_s[tid] = wf[tid];
    }
    __syncthreads();
    const float* P = g_hUVBC;
    const float* Q = g_hUVBC + (size_t)NN * D;
    {
        int row = tid >> 1, half = tid & 1;
        const float* p = P + (size_t)s_src[row] * D + half * 64;
        const float* q = Q + (size_t)s_dst[row] * D + half * 64;
#pragma unroll
        for (int i = 0; i < 16; i++) {
            int colb = half * 64 + i * 4;
            float4 pv = *reinterpret_cast<const float4*>(p + i * 4);
            float4 qv = *reinterpret_cast<const float4*>(q + i * 4);
            float4 mv = *reinterpret_cast<const float4*>(vmoy_s + colb);
            float4 v;
            v.x = f2tf(fmaxf(pv.x + qv.x + mv.x, 0.f));
            v.y = f2tf(fmaxf(pv.y + qv.y + mv.y, 0.f));
            v.z = f2tf(fmaxf(pv.z + qv.z + mv.z, 0.f));
            v.w = f2tf(fmaxf(pv.w + qv.w + mv.w, 0.f));
            *reinterpret_cast<float4*>(X + (colb >> 4) * (128 * AS_STRIDE) + row * AS_STRIDE +
                                       (colb & 15)) = v;
        }
    }
    __syncthreads();
    int wid = tid >> 5, lane = tid & 31;
    int warp_m = wid & 3, warp_n = wid >> 2;
    int r = lane >> 2, c = lane & 3;
    mlp_stage<true>(X, Wb, Wk, Wk_b, tid, warp_m, warp_n, r, c);
    mlp_stage<false>(X, Wb, Wk + 16384, Wk_b + 128, tid, warp_m, warp_n, r, c);
    if (tid < 128) {
        float s = 0.f;
#pragma unroll
        for (int kt = 0; kt < 8; kt++)
#pragma unroll
            for (int k = 0; k < 16; k++)
                s = fmaf(X[kt * (128 * AS_STRIDE) + tid * AS_STRIDE + k], wf_s[kt * 16 + k], s);
        out[m0 + tid] = 1.f / (1.f + expf(-(s + wfb[0])));
    }
}

// ---------------- host -------------------------------------------------------
extern "C" void kernel_launch(void* const* d_in, const int* in_sizes, int n_in,
                              void* d_out, int out_size) {
    const float* h_in = (const float*)d_in[0];
    const float* e_in = (const float*)d_in[1];
    const float* emb_n_w = (const float*)d_in[2];
    const float* emb_n_b = (const float*)d_in[3];
    const float* emb_e_w = (const float*)d_in[4];
    const float* emb_e_b = (const float*)d_in[5];
    const float* Uw = (const float*)d_in[6];
    const float* Vw = (const float*)d_in[7];
    const float* Aw = (const float*)d_in[8];
    const float* Bw = (const float*)d_in[9];
    const float* Cw = (const float*)d_in[10];
    const float* W0_w = (const float*)d_in[11];
    const float* W0_b = (const float*)d_in[12];
    const float* Wk_w = (const float*)d_in[13];
    const float* Wk_b = (const float*)d_in[14];
    const float* Wf_w = (const float*)d_in[15];
    const float* Wf_b = (const float*)d_in[16];
    const int* src = (const int*)d_in[17];
    const int* dst = (const int*)d_in[18];
    float* out = (float*)d_out;

    float *h0, *h1, *huvbc, *wpack, *psum, *psq, *epsum, *epsq, *gmean, *grstd, *gemean, *gerstd;
    cudaGetSymbolAddress((void**)&h0, g_h0);
    cudaGetSymbolAddress((void**)&h1, g_h1);
    cudaGetSymbolAddress((void**)&huvbc, g_hUVBC);
    cudaGetSymbolAddress((void**)&wpack, g_wpack);
    cudaGetSymbolAddress((void**)&psum, g_psum);
    cudaGetSymbolAddress((void**)&psq, g_psq);
    cudaGetSymbolAddress((void**)&epsum, g_epsum);
    cudaGetSymbolAddress((void**)&epsq, g_epsq);
    cudaGetSymbolAddress((void**)&gmean, g_mean);
    cudaGetSymbolAddress((void**)&grstd, g_rstd);
    cudaGetSymbolAddress((void**)&gemean, g_emean);
    cudaGetSymbolAddress((void**)&gerstd, g_erstd);

    cudaFuncSetAttribute(readout_fused, cudaFuncAttributeMaxDynamicSharedMemorySize, 103424);

    const int GN = (NN + 127) / 128;  // 391

    pack_weights<<<960, 256>>>(Uw, Vw, Bw, Cw, Aw, W0_w, Wk_w);
    fold_WA<<<1, 128>>>(emb_e_w, emb_e_b);
    embed_kernel<16, 8><<<(NN + 7) / 8, 128>>>(h_in, emb_n_w, emb_n_b, h0, NN);

    // ---- layer 0 ----
    fill_neginf_kernel<<<(NN * D / 4 + 255) / 256, 256>>>();
    gemm_tf32<<<dim3(GN, 4), 256>>>(h0, wpack, 16384, huvbc, (long)NN * D, NN);
    edge_l0_fused<<<GEB, 256>>>(e_in, emb_e_w, emb_e_b, src, dst);
    finalize_stats<<<1, 128>>>(epsum, epsq, GEB, 1.f / (float)NE, gemean, gerstd);
    node_pre_stats<<<NBS, 128>>>();
    finalize_stats<<<1, 128>>>(psum, psq, NBS, 1.f / (float)NN, gmean, grstd);
    node_update<<<(NN * D + 255) / 256, 256>>>(h0, h1);

    // ---- layer 1 ----
    fill_neginf_kernel<<<(NN * D / 4 + 255) / 256, 256>>>();
    gemm_tf32<<<dim3(GN, 2), 256>>>(h1, wpack + 81920, 16384, huvbc, (long)NN * D, NN);
    edge_update_scatter<<<(NE * D + 255) / 256, 256>>>(e_in, emb_e_w, emb_e_b, src, dst);
    node_pre_stats<<<NBS, 128>>>();
    finalize_stats<<<1, 128>>>(psum, psq, NBS, 1.f / (float)NN, gmean, grstd);
    node_update<<<(NN * D + 255) / 256, 256>>>(h1, h0);

    // ---- readout (final h is in h0) ----
    moy_partial<<<NBS, 128>>>(h0);
    finalize_moy_vmoy<<<1, 128>>>(W0_b);
    gemm_tf32<<<dim3(GN, 2), 256>>>(h0, wpack + 163840 + 16384, 16384, huvbc, (long)NN * D, NN);
    readout_fused<<<GEB, 256, 103424>>>(src, dst, wpack + 212992, Wk_b, Wf_w, Wf_b, out);
}

// round 16
// speedup vs baseline: 1.0209x; 1.0209x over previous
#include <cuda_runtime.h>
#include <math.h>

#define NN 50000
#define NE 400000
#define D 128
#define NBS 512
#define GEB 3125  // NE/128

// ---------------- scratch ---------------------------------------------------
__device__ float g_h0[NN * D];
__device__ float g_h1[NN * D];
__device__ float g_hUVBC[4 * NN * D];  // U,V,B,C results; later P,Q
__device__ unsigned g_agg[NN * D];     // order-preserving float keys
__device__ float g_psum[NBS * D];
__device__ float g_psq[NBS * D];
__device__ float g_epsum[GEB * D];
__device__ float g_epsq[GEB * D];
__device__ float g_mean[D];
__device__ float g_rstd[D];
__device__ float g_emean[D];
__device__ float g_erstd[D];
__device__ float g_vmoy[D];
__device__ float g_WA[9 * D];  // folded [emb_e_w; b] @ A0
__device__ float g_wpack[245760];

// ---------------- helpers ---------------------------------------------------
__device__ __forceinline__ float f2tf(float x) {
    unsigned r;
    asm("cvt.rna.tf32.f32 %0, %1;" : "=r"(r) : "f"(x));
    return __uint_as_float(r);
}

// order-preserving float<->uint key (single unconditional atomicMax path)
__device__ __forceinline__ unsigned fkey(float x) {
    unsigned b = __float_as_uint(x);
    return ((int)b < 0) ? ~b : (b | 0x80000000u);
}
__device__ __forceinline__ float funkey(unsigned k) {
    return __uint_as_float(((int)k < 0) ? (k & 0x7fffffffu) : ~k);
}
#define KEY_NEGINF 0x007FFFFFu  // fkey(-inf)

__device__ __forceinline__ void cpa16(void* smem, const void* g, bool pred) {
    unsigned s = (unsigned)__cvta_generic_to_shared(smem);
    int sz = pred ? 16 : 0;
    asm volatile("cp.async.cg.shared.global [%0], [%1], 16, %2;" ::"r"(s), "l"(g), "r"(sz));
}
__device__ __forceinline__ void cpa_commit() { asm volatile("cp.async.commit_group;"); }
template <int N>
__device__ __forceinline__ void cpa_wait() { asm volatile("cp.async.wait_group %0;" ::"n"(N)); }

__device__ __forceinline__ void mma_tf32(float* d, const unsigned* a, const unsigned* b) {
    asm volatile(
        "mma.sync.aligned.m16n8k8.row.col.f32.tf32.tf32.f32 "
        "{%0,%1,%2,%3}, {%4,%5,%6,%7}, {%8,%9}, {%0,%1,%2,%3};"
        : "+f"(d[0]), "+f"(d[1]), "+f"(d[2]), "+f"(d[3])
        : "r"(a[0]), "r"(a[1]), "r"(a[2]), "r"(a[3]), "r"(b[0]), "r"(b[1]));
}

#define AS_STRIDE 20
#define BS_STRIDE 136

__device__ __forceinline__ void do_kt(const float* __restrict__ As, const float* __restrict__ Bs,
                                      float (&acc)[2][8][4], int warp_m, int warp_n, int r,
                                      int c) {
#pragma unroll
    for (int kk = 0; kk < 2; kk++) {
        unsigned afr[2][4], bfr[8][2];
#pragma unroll
        for (int mt = 0; mt < 2; mt++) {
            int row0 = warp_m * 32 + mt * 16;
            afr[mt][0] = __float_as_uint(As[(row0 + r) * AS_STRIDE + kk * 8 + c]);
            afr[mt][1] = __float_as_uint(As[(row0 + 8 + r) * AS_STRIDE + kk * 8 + c]);
            afr[mt][2] = __float_as_uint(As[(row0 + r) * AS_STRIDE + kk * 8 + c + 4]);
            afr[mt][3] = __float_as_uint(As[(row0 + 8 + r) * AS_STRIDE + kk * 8 + c + 4]);
        }
#pragma unroll
        for (int nt = 0; nt < 8; nt++) {
            int col0 = warp_n * 64 + nt * 8;
            bfr[nt][0] = __float_as_uint(Bs[(kk * 8 + c) * BS_STRIDE + col0 + r]);
            bfr[nt][1] = __float_as_uint(Bs[(kk * 8 + c + 4) * BS_STRIDE + col0 + r]);
        }
#pragma unroll
        for (int mt = 0; mt < 2; mt++)
#pragma unroll
            for (int nt = 0; nt < 8; nt++) mma_tf32(acc[mt][nt], afr[mt], bfr[nt]);
    }
}

// ---------------- weight packing --------------------------------------------
// l*81920 + {U:0,V:16384,B:32768,C:49152,Ae:65536}; W0:163840(3x16384); Wk:212992(2x16384)
__global__ void pack_weights(const float* __restrict__ U, const float* __restrict__ V,
                             const float* __restrict__ B, const float* __restrict__ C,
                             const float* __restrict__ A, const float* __restrict__ W0,
                             const float* __restrict__ Wk) {
    int i = blockIdx.x * 256 + threadIdx.x;
    if (i >= 245760) return;
    int c = i >> 14, r = i & 16383;
    float v;
    if (c < 10) {
        int l = c / 5, w = c % 5;
        const float* base = (w == 0) ? U : (w == 1) ? V : (w == 2) ? B : (w == 3) ? C : A;
        v = base[l * 16384 + r];
    } else if (c < 13) {
        v = W0[(c - 10) * 16384 + r];
    } else {
        v = Wk[(c - 13) * 16384 + r];
    }
    g_wpack[i] = f2tf(v);
}

// ---------------- fold edge-embed into A0: WA = [emb_e_w; b] @ A0 ------------
__global__ void fold_WA(const float* __restrict__ ew, const float* __restrict__ ebias) {
    int c = threadIdx.x;  // 128
    const float* A = g_wpack + 65536;  // tf32-rounded A (layer 0)
    for (int f = 0; f < 8; f++) {
        float acc = 0.f;
        for (int k = 0; k < 128; k++) acc = fmaf(ew[f * 128 + k], A[k * 128 + c], acc);
        g_WA[f * 128 + c] = acc;
    }
    float acc = 0.f;
    for (int k = 0; k < 128; k++) acc = fmaf(ebias[k], A[k * 128 + c], acc);
    g_WA[8 * 128 + c] = acc;
}

// ---------------- node embedding (outputs tf32-rounded) ----------------------
template <int F, int ROWS>
__global__ void embed_kernel(const float* __restrict__ X, const float* __restrict__ W,
                             const float* __restrict__ b, float* __restrict__ out, int M) {
    __shared__ float ws[F * D];
    __shared__ float xs[ROWS][F];
    int tid = threadIdx.x;  // 128
    for (int i = tid; i < F * D; i += 128) ws[i] = W[i];
    float bias = b[tid];
    int r0 = blockIdx.x * ROWS;
    for (int i = tid; i < ROWS * F; i += 128) {
        int r = i / F, f = i % F;
        xs[r][f] = (r0 + r < M) ? X[(size_t)(r0 + r) * F + f] : 0.f;
    }
    __syncthreads();
    for (int r = 0; r < ROWS; r++) {
        if (r0 + r >= M) break;
        float acc = bias;
#pragma unroll
        for (int f = 0; f < F; f++) acc = fmaf(xs[r][f], ws[f * D + tid], acc);
        out[(size_t)(r0 + r) * D + tid] = f2tf(acc);
    }
}

// ---------------- plain TF32 GEMM: C[M,128]=A[M,128]@W -----------------------
struct SmemGemm {
    float As[2][128 * AS_STRIDE];
    float Bs[2][16 * BS_STRIDE];
};

__global__ __launch_bounds__(256) void gemm_tf32(const float* __restrict__ A,
                                                 const float* __restrict__ Wbase, int wstride,
                                                 float* __restrict__ Cbase, long cstride, int M) {
    __shared__ SmemGemm sm;
    const float* W = Wbase + (size_t)blockIdx.y * wstride;
    float* Cgm = Cbase + (size_t)blockIdx.y * cstride;
    int tid = threadIdx.x;
    int wid = tid >> 5, lane = tid & 31;
    int warp_m = wid & 3, warp_n = wid >> 2;
    int r = lane >> 2, c = lane & 3;
    int m0 = blockIdx.x * 128;

    float acc[2][8][4];
#pragma unroll
    for (int mt = 0; mt < 2; mt++)
#pragma unroll
        for (int nt = 0; nt < 8; nt++)
#pragma unroll
            for (int j = 0; j < 4; j++) acc[mt][nt][j] = 0.f;

    auto loadA = [&](int buf, int kt) {
#pragma unroll
        for (int i = 0; i < 2; i++) {
            int f = tid + i * 256;
            int row = f >> 2, k4 = f & 3;
            bool p = (m0 + row) < M;
            const float* g = A + (size_t)(m0 + row) * D + kt * 16 + k4 * 4;
            cpa16(&sm.As[buf][row * AS_STRIDE + k4 * 4], p ? g : (const void*)W, p);
        }
    };
    auto loadB = [&](int buf, int kt) {
#pragma unroll
        for (int i = 0; i < 2; i++) {
            int f = tid + i * 256;
            int k = f >> 5, n4 = f & 31;
            cpa16(&sm.Bs[buf][k * BS_STRIDE + n4 * 4], W + (size_t)(kt * 16 + k) * D + n4 * 4,
                  true);
        }
    };

    loadA(0, 0); loadB(0, 0); cpa_commit();
    loadA(1, 1); loadB(1, 1); cpa_commit();
    for (int kt = 0; kt < 8; kt++) {
        int buf = kt & 1;
        if (kt + 1 < 8) cpa_wait<1>(); else cpa_wait<0>();
        __syncthreads();
        do_kt(sm.As[buf], sm.Bs[buf], acc, warp_m, warp_n, r, c);
        __syncthreads();
        if (kt + 2 < 8) { loadA(buf, kt + 2); loadB(buf, kt + 2); cpa_commit(); }
    }

    int c2 = c * 2;
#pragma unroll
    for (int nt = 0; nt < 8; nt++) {
        int col = warp_n * 64 + nt * 8 + c2;
#pragma unroll
        for (int mt = 0; mt < 2; mt++) {
            int row = m0 + warp_m * 32 + mt * 16 + r;
            if (row < M)
                *reinterpret_cast<float2*>(Cgm + (size_t)row * D + col) =
                    make_float2(acc[mt][nt][0], acc[mt][nt][1]);
            if (row + 8 < M)
                *reinterpret_cast<float2*>(Cgm + (size_t)(row + 8) * D + col) =
                    make_float2(acc[mt][nt][2], acc[mt][nt][3]);
        }
    }
}

// ---- l=0 edge kernel (rank-9): stats over t2 = e_in@WA + WA[8] + hB[dst] +
//      hC[src] (t2 NOT materialized); gate e0 = f2tf(ebias + e_in@We);
//      fused scatter-max (single-path key atomics).
__global__ __launch_bounds__(256) void edge_l0_fused(const float* __restrict__ e_in,
                                                     const float* __restrict__ ew,
                                                     const float* __restrict__ ebias,
                                                     const int* __restrict__ src,
                                                     const int* __restrict__ dst) {
    __shared__ float s_ein[128 * 8];
    __shared__ int s_src[128];
    __shared__ int s_dst[128];
    __shared__ float red[4 * 256];
    int tid = threadIdx.x;
    int m0 = blockIdx.x * 128;
    if (tid < 128) {
        s_src[tid] = src[m0 + tid];
        s_dst[tid] = dst[m0 + tid];
    }
    for (int i = tid; i < 1024; i += 256) s_ein[i] = e_in[(size_t)m0 * 8 + i];

    int cp = tid & 63;   // column pair
    int c0 = cp * 2;
    int eg = tid >> 6;   // edge group 0..3
    float wa[9][2], we[8][2], eb2[2];
#pragma unroll
    for (int f = 0; f < 9; f++) {
        wa[f][0] = g_WA[f * 128 + c0];
        wa[f][1] = g_WA[f * 128 + c0 + 1];
    }
#pragma unroll
    for (int f = 0; f < 8; f++) {
        we[f][0] = ew[f * 128 + c0];
        we[f][1] = ew[f * 128 + c0 + 1];
    }
    eb2[0] = ebias[c0];
    eb2[1] = ebias[c0 + 1];
    __syncthreads();

    const float* hV = g_hUVBC + (size_t)NN * D;
    const float* hB = g_hUVBC + 2 * (size_t)NN * D;
    const float* hC = g_hUVBC + 3 * (size_t)NN * D;
    float sa = 0.f, qa = 0.f, sb = 0.f, qb = 0.f;
    for (int it = 0; it < 32; it++) {
        int row = it * 4 + eg;
        const float* er = s_ein + row * 8;
        float ta = wa[8][0], tb = wa[8][1];
        float ea = eb2[0], eb_ = eb2[1];
#pragma unroll
        for (int f = 0; f < 8; f++) {
            float x = er[f];
            ta = fmaf(x, wa[f][0], ta);
            tb = fmaf(x, wa[f][1], tb);
            ea = fmaf(x, we[f][0], ea);
            eb_ = fmaf(x, we[f][1], eb_);
        }
        ea = f2tf(ea);
        eb_ = f2tf(eb_);
        int s = s_src[row], d = s_dst[row];
        float2 hb = *reinterpret_cast<const float2*>(hB + (size_t)d * D + c0);
        float2 hc = *reinterpret_cast<const float2*>(hC + (size_t)s * D + c0);
        float2 hv = *reinterpret_cast<const float2*>(hV + (size_t)s * D + c0);
        float va = ta + hb.x + hc.x;
        float vb = tb + hb.y + hc.y;
        sa += va; qa += va * va;
        sb += vb; qb += vb * vb;
        float wga = 1.f / (1.f + __expf(-ea));
        float wgb = 1.f / (1.f + __expf(-eb_));
        atomicMax(&g_agg[(size_t)d * D + c0], fkey(hv.x * wga));
        atomicMax(&g_agg[(size_t)d * D + c0 + 1], fkey(hv.y * wgb));
    }
    red[tid] = sa;
    red[256 + tid] = qa;
    red[512 + tid] = sb;
    red[768 + tid] = qb;
    __syncthreads();
    if (tid < 64) {
        float S0 = red[tid] + red[tid + 64] + red[tid + 128] + red[tid + 192];
        float Q0 = red[256 + tid] + red[256 + tid + 64] + red[256 + tid + 128] + red[256 + tid + 192];
        float S1 = red[512 + tid] + red[512 + tid + 64] + red[512 + tid + 128] + red[512 + tid + 192];
        float Q1 = red[768 + tid] + red[768 + tid + 64] + red[768 + tid + 128] + red[768 + tid + 192];
        g_epsum[blockIdx.x * D + tid * 2] = S0;
        g_epsq[blockIdx.x * D + tid * 2] = Q0;
        g_epsum[blockIdx.x * D + tid * 2 + 1] = S1;
        g_epsq[blockIdx.x * D + tid * 2 + 1] = Q1;
    }
}

// ---- l=1: fused edge-update + scatter-max, 1 elem/thread; e0/t2 recomputed --
__global__ void edge_update_scatter(const float* __restrict__ e_in, const float* __restrict__ ew,
                                    const float* __restrict__ ebias, const int* __restrict__ src,
                                    const int* __restrict__ dst) {
    int idx = blockIdx.x * blockDim.x + threadIdx.x;
    if (idx >= NE * D) return;
    int eidx = idx >> 7;
    int d = idx & 127;
    int s = __ldg(src + eidx);
    int t = __ldg(dst + eidx);
    const float* er = e_in + (size_t)eidx * 8;
    float ta = __ldg(g_WA + 8 * 128 + d);
    float e0 = __ldg(ebias + d);
#pragma unroll
    for (int f = 0; f < 8; f++) {
        float x = __ldg(er + f);
        ta = fmaf(x, __ldg(g_WA + f * 128 + d), ta);
        e0 = fmaf(x, __ldg(ew + f * 128 + d), e0);
    }
    e0 = f2tf(e0);
    const float* hV = g_hUVBC + (size_t)NN * D;
    const float* hB = g_hUVBC + 2 * (size_t)NN * D;
    const float* hC = g_hUVBC + 3 * (size_t)NN * D;
    float va = ta + hB[(size_t)t * D + d] + hC[(size_t)s * D + d];
    float x = (va - g_emean[d]) * g_erstd[d];
    float e1 = f2tf(e0 + fmaxf(x, 0.f));
    float w = 1.f / (1.f + __expf(-e1));
    atomicMax(&g_agg[(size_t)t * D + d], fkey(hV[(size_t)s * D + d] * w));
}

// ---------------- fill agg with key(-inf) ------------------------------------
__global__ void fill_neginf_kernel() {
    int i = blockIdx.x * blockDim.x + threadIdx.x;
    uint4 v = make_uint4(KEY_NEGINF, KEY_NEGINF, KEY_NEGINF, KEY_NEGINF);
    if (i < NN * D / 4) reinterpret_cast<uint4*>(g_agg)[i] = v;
}

// ---------------- BN stats ---------------------------------------------------
__global__ void node_pre_stats() {
    int c = threadIdx.x;
    const float* hU = g_hUVBC;
    float s = 0.f, q = 0.f;
    for (int r = blockIdx.x; r < NN; r += gridDim.x) {
        float a = funkey(g_agg[(size_t)r * D + c]);
        if (!isfinite(a)) a = 0.f;
        float v = hU[(size_t)r * D + c] + a;
        s += v;
        q += v * v;
    }
    g_psum[blockIdx.x * D + c] = s;
    g_psq[blockIdx.x * D + c] = q;
}

__global__ void finalize_stats(const float* __restrict__ psum, const float* __restrict__ psq,
                               int nb, float inv_count, float* __restrict__ omean,
                               float* __restrict__ orstd) {
    int c = threadIdx.x;
    double s = 0.0, q = 0.0;
    for (int i = 0; i < nb; i++) {
        s += (double)psum[i * D + c];
        q += (double)psq[i * D + c];
    }
    double m = s * (double)inv_count;
    double v = q * (double)inv_count - m * m;
    omean[c] = (float)m;
    orstd[c] = rsqrtf((float)v + 1e-5f);
}

__global__ void node_update(const float* __restrict__ h, float* __restrict__ hn) {
    int i = blockIdx.x * blockDim.x + threadIdx.x;
    if (i >= NN * D) return;
    int c = i & 127;
    const float* hU = g_hUVBC;
    float a = funkey(g_agg[i]);
    if (!isfinite(a)) a = 0.f;
    float v = hU[i] + a;
    float x = (v - g_mean[c]) * g_rstd[c];
    hn[i] = f2tf(h[i] + fmaxf(x, 0.f));
}

// ---------------- moy + vmoy -------------------------------------------------
__global__ void moy_partial(const float* __restrict__ h) {
    int c = threadIdx.x;
    float s = 0.f;
    for (int r = blockIdx.x; r < NN; r += gridDim.x) s += h[(size_t)r * D + c];
    g_psum[blockIdx.x * D + c] = s;
}

__global__ void finalize_moy_vmoy(const float* __restrict__ W0_b) {
    __shared__ float moy_s[D];
    int c = threadIdx.x;
    double s = 0.0;
    for (int i = 0; i < NBS; i++) s += (double)g_psum[i * D + c];
    moy_s[c] = (float)(s / (double)NN);
    __syncthreads();
    float v = W0_b[c];
    const float* W0a = g_wpack + 163840;
#pragma unroll 4
    for (int k = 0; k < D; k++) v = fmaf(moy_s[k], W0a[k * D + c], v);
    g_vmoy[c] = v;
}

// ---------------- fused readout MLP ------------------------------------------
template <bool ROUND>
__device__ __forceinline__ void mlp_stage(float* __restrict__ X, float* __restrict__ Wb,
                                          const float* __restrict__ Wg,
                                          const float* __restrict__ bias, int tid, int warp_m,
                                          int warp_n, int r, int c) {
    float acc[2][8][4];
#pragma unroll
    for (int mt = 0; mt < 2; mt++)
#pragma unroll
        for (int nt = 0; nt < 8; nt++)
#pragma unroll
            for (int j = 0; j < 4; j++) acc[mt][nt][j] = 0.f;

    auto loadW = [&](int buf, int kt) {
#pragma unroll
        for (int i = 0; i < 2; i++) {
            int f = tid + i * 256;
            int k = f >> 5, n4 = f & 31;
            cpa16(&Wb[buf * (16 * BS_STRIDE) + k * BS_STRIDE + n4 * 4],
                  Wg + (size_t)(kt * 16 + k) * D + n4 * 4, true);
        }
    };
    loadW(0, 0); cpa_commit();
    loadW(1, 1); cpa_commit();
    for (int kt = 0; kt < 8; kt++) {
        int buf = kt & 1;
        if (kt + 1 < 8) cpa_wait<1>(); else cpa_wait<0>();
        __syncthreads();
        do_kt(X + kt * (128 * AS_STRIDE), Wb + buf * (16 * BS_STRIDE), acc, warp_m, warp_n, r, c);
        __syncthreads();
        if (kt + 2 < 8) { loadW(buf, kt + 2); cpa_commit(); }
    }
    int c2 = c * 2;
#pragma unroll
    for (int nt = 0; nt < 8; nt++) {
        int col = warp_n * 64 + nt * 8 + c2;
        float b0 = bias[col], b1 = bias[col + 1];
#pragma unroll
        for (int mt = 0; mt < 2; mt++) {
            int row = warp_m * 32 + mt * 16 + r;
            float v0 = fmaxf(acc[mt][nt][0] + b0, 0.f);
            float v1 = fmaxf(acc[mt][nt][1] + b1, 0.f);
            float v2 = fmaxf(acc[mt][nt][2] + b0, 0.f);
            float v3 = fmaxf(acc[mt][nt][3] + b1, 0.f);
            if (ROUND) { v0 = f2tf(v0); v1 = f2tf(v1); v2 = f2tf(v2); v3 = f2tf(v3); }
            X[(col >> 4) * (128 * AS_STRIDE) + row * AS_STRIDE + (col & 15)] = v0;
            X[(col >> 4) * (128 * AS_STRIDE) + (row + 8) * AS_STRIDE + (col & 15)] = v2;
            X[((col + 1) >> 4) * (128 * AS_STRIDE) + row * AS_STRIDE + ((col + 1) & 15)] = v1;
            X[((col + 1) >> 4) * (128 * AS_STRIDE) + (row + 8) * AS_STRIDE + ((col + 1) & 15)] = v3;
        }
    }
    __syncthreads();
}

__global__ __launch_bounds__(256) void readout_fused(const int* __restrict__ src,
                                                     const int* __restrict__ dst,
                                                     const float* __restrict__ Wk,
                                                     const float* __restrict__ Wk_b,
                                                     const float* __restrict__ wf,
                                                     const float* __restrict__ wfb,
                                                     float* __restrict__ out) {
    extern __shared__ float dyn[];
    float* X = dyn;                       // 8*128*20 = 20480
    float* Wb = dyn + 20480;              // 2*16*136 = 4352
    float* vmoy_s = Wb + 4352;            // 128
    float* wf_s = vmoy_s + 128;           // 128
    int* s_src = (int*)(wf_s + 128);      // 128
    int* s_dst = s_src + 128;             // 128
    int tid = threadIdx.x;
    int m0 = blockIdx.x * 128;
    if (tid < 128) {
        s_src[tid] = src[m0 + tid];
        s_dst[tid] = dst[m0 + tid];
        vmoy_s[tid] = g_vmoy[tid];
        wf_s[tid] = wf[tid];
    }
    __syncthreads();
    const float* P = g_hUVBC;
    const float* Q = g_hUVBC + (size_t)NN * D;
    {
        int row = tid >> 1, half = tid & 1;
        const float* p = P + (size_t)s_src[row] * D + half * 64;
        const float* q = Q + (size_t)s_dst[row] * D + half * 64;
#pragma unroll
        for (int i = 0; i < 16; i++) {
            int colb = half * 64 + i * 4;
            float4 pv = *reinterpret_cast<const float4*>(p + i * 4);
            float4 qv = *reinterpret_cast<const float4*>(q + i * 4);
            float4 mv = *reinterpret_cast<const float4*>(vmoy_s + colb);
            float4 v;
            v.x = f2tf(fmaxf(pv.x + qv.x + mv.x, 0.f));
            v.y = f2tf(fmaxf(pv.y + qv.y + mv.y, 0.f));
            v.z = f2tf(fmaxf(pv.z + qv.z + mv.z, 0.f));
            v.w = f2tf(fmaxf(pv.w + qv.w + mv.w, 0.f));
            *reinterpret_cast<float4*>(X + (colb >> 4) * (128 * AS_STRIDE) + row * AS_STRIDE +
                                       (colb & 15)) = v;
        }
    }
    __syncthreads();
    int wid = tid >> 5, lane = tid & 31;
    int warp_m = wid & 3, warp_n = wid >> 2;
    int r = lane >> 2, c = lane & 3;
    mlp_stage<true>(X, Wb, Wk, Wk_b, tid, warp_m, warp_n, r, c);
    mlp_stage<false>(X, Wb, Wk + 16384, Wk_b + 128, tid, warp_m, warp_n, r, c);
    if (tid < 128) {
        float s = 0.f;
#pragma unroll
        for (int kt = 0; kt < 8; kt++)
#pragma unroll
            for (int k = 0; k < 16; k++)
                s = fmaf(X[kt * (128 * AS_STRIDE) + tid * AS_STRIDE + k], wf_s[kt * 16 + k], s);
        out[m0 + tid] = 1.f / (1.f + expf(-(s + wfb[0])));
    }
}

// ---------------- host -------------------------------------------------------
extern "C" void kernel_launch(void* const* d_in, const int* in_sizes, int n_in,
                              void* d_out, int out_size) {
    const float* h_in = (const float*)d_in[0];
    const float* e_in = (const float*)d_in[1];
    const float* emb_n_w = (const float*)d_in[2];
    const float* emb_n_b = (const float*)d_in[3];
    const float* emb_e_w = (const float*)d_in[4];
    const float* emb_e_b = (const float*)d_in[5];
    const float* Uw = (const float*)d_in[6];
    const float* Vw = (const float*)d_in[7];
    const float* Aw = (const float*)d_in[8];
    const float* Bw = (const float*)d_in[9];
    const float* Cw = (const float*)d_in[10];
    const float* W0_w = (const float*)d_in[11];
    const float* W0_b = (const float*)d_in[12];
    const float* Wk_w = (const float*)d_in[13];
    const float* Wk_b = (const float*)d_in[14];
    const float* Wf_w = (const float*)d_in[15];
    const float* Wf_b = (const float*)d_in[16];
    const int* src = (const int*)d_in[17];
    const int* dst = (const int*)d_in[18];
    float* out = (float*)d_out;

    float *h0, *h1, *huvbc, *wpack, *psum, *psq, *epsum, *epsq, *gmean, *grstd, *gemean, *gerstd;
    cudaGetSymbolAddress((void**)&h0, g_h0);
    cudaGetSymbolAddress((void**)&h1, g_h1);
    cudaGetSymbolAddress((void**)&huvbc, g_hUVBC);
    cudaGetSymbolAddress((void**)&wpack, g_wpack);
    cudaGetSymbolAddress((void**)&psum, g_psum);
    cudaGetSymbolAddress((void**)&psq, g_psq);
    cudaGetSymbolAddress((void**)&epsum, g_epsum);
    cudaGetSymbolAddress((void**)&epsq, g_epsq);
    cudaGetSymbolAddress((void**)&gmean, g_mean);
    cudaGetSymbolAddress((void**)&grstd, g_rstd);
    cudaGetSymbolAddress((void**)&gemean, g_emean);
    cudaGetSymbolAddress((void**)&gerstd, g_erstd);

    cudaFuncSetAttribute(readout_fused, cudaFuncAttributeMaxDynamicSharedMemorySize, 103424);

    const int GN = (NN + 127) / 128;  // 391

    pack_weights<<<960, 256>>>(Uw, Vw, Bw, Cw, Aw, W0_w, Wk_w);
    fold_WA<<<1, 128>>>(emb_e_w, emb_e_b);
    embed_kernel<16, 8><<<(NN + 7) / 8, 128>>>(h_in, emb_n_w, emb_n_b, h0, NN);

    // ---- layer 0 ----
    fill_neginf_kernel<<<(NN * D / 4 + 255) / 256, 256>>>();
    gemm_tf32<<<dim3(GN, 4), 256>>>(h0, wpack, 16384, huvbc, (long)NN * D, NN);
    edge_l0_fused<<<GEB, 256>>>(e_in, emb_e_w, emb_e_b, src, dst);
    finalize_stats<<<1, 128>>>(epsum, epsq, GEB, 1.f / (float)NE, gemean, gerstd);
    node_pre_stats<<<NBS, 128>>>();
    finalize_stats<<<1, 128>>>(psum, psq, NBS, 1.f / (float)NN, gmean, grstd);
    node_update<<<(NN * D + 255) / 256, 256>>>(h0, h1);

    // ---- layer 1 ----
    fill_neginf_kernel<<<(NN * D / 4 + 255) / 256, 256>>>();
    gemm_tf32<<<dim3(GN, 2), 256>>>(h1, wpack + 81920, 16384, huvbc, (long)NN * D, NN);
    edge_update_scatter<<<(NE * D + 255) / 256, 256>>>(e_in, emb_e_w, emb_e_b, src, dst);
    node_pre_stats<<<NBS, 128>>>();
    finalize_stats<<<1, 128>>>(psum, psq, NBS, 1.f / (float)NN, gmean, grstd);
    node_update<<<(NN * D + 255) / 256, 256>>>(h1, h0);

    // ---- readout (final h is in h0) ----
    moy_partial<<<NBS, 128>>>(h0);
    finalize_moy_vmoy<<<1, 128>>>(W0_b);
    gemm_tf32<<<dim3(GN, 2), 256>>>(h0, wpack + 163840 + 16384, 16384, huvbc, (long)NN * D, NN);
    readout_fused<<<GEB, 256, 103424>>>(src, dst, wpack + 212992, Wk_b, Wf_w, Wf_b, out);
}

// round 17
// speedup vs baseline: 1.0960x; 1.0736x over previous
#include <cuda_runtime.h>
#include <math.h>

#define NN 50000
#define NE 400000
#define D 128
#define NBS 512
#define GEB 3125  // NE/128

// ---------------- scratch ---------------------------------------------------
__device__ float g_h0[NN * D];
__device__ float g_h1[NN * D];
__device__ float g_hUVBC[4 * NN * D];  // U,V,B,C results; later P,Q
__device__ unsigned g_agg[NN * D];     // order-preserving float keys
__device__ float g_psum[NBS * D];
__device__ float g_psq[NBS * D];
__device__ float g_epsum[GEB * D];
__device__ float g_epsq[GEB * D];
__device__ float g_mean[D];
__device__ float g_rstd[D];
__device__ float g_emean[D];
__device__ float g_erstd[D];
__device__ float g_vmoy[D];
__device__ float g_WA[9 * D];  // folded [emb_e_w; b] @ A0
__device__ float g_wpack[245760];

// ---------------- helpers ---------------------------------------------------
__device__ __forceinline__ float f2tf(float x) {
    unsigned r;
    asm("cvt.rna.tf32.f32 %0, %1;" : "=r"(r) : "f"(x));
    return __uint_as_float(r);
}

// order-preserving float<->uint key (single unconditional atomicMax path)
__device__ __forceinline__ unsigned fkey(float x) {
    unsigned b = __float_as_uint(x);
    return ((int)b < 0) ? ~b : (b | 0x80000000u);
}
__device__ __forceinline__ float funkey(unsigned k) {
    return __uint_as_float(((int)k < 0) ? (k & 0x7fffffffu) : ~k);
}
#define KEY_NEGINF 0x007FFFFFu  // fkey(-inf)

__device__ __forceinline__ void cpa16(void* smem, const void* g, bool pred) {
    unsigned s = (unsigned)__cvta_generic_to_shared(smem);
    int sz = pred ? 16 : 0;
    asm volatile("cp.async.cg.shared.global [%0], [%1], 16, %2;" ::"r"(s), "l"(g), "r"(sz));
}
__device__ __forceinline__ void cpa_commit() { asm volatile("cp.async.commit_group;"); }
template <int N>
__device__ __forceinline__ void cpa_wait() { asm volatile("cp.async.wait_group %0;" ::"n"(N)); }

__device__ __forceinline__ void mma_tf32(float* d, const unsigned* a, const unsigned* b) {
    asm volatile(
        "mma.sync.aligned.m16n8k8.row.col.f32.tf32.tf32.f32 "
        "{%0,%1,%2,%3}, {%4,%5,%6,%7}, {%8,%9}, {%0,%1,%2,%3};"
        : "+f"(d[0]), "+f"(d[1]), "+f"(d[2]), "+f"(d[3])
        : "r"(a[0]), "r"(a[1]), "r"(a[2]), "r"(a[3]), "r"(b[0]), "r"(b[1]));
}

#define AS_STRIDE 20
#define BS_STRIDE 136

__device__ __forceinline__ void do_kt(const float* __restrict__ As, const float* __restrict__ Bs,
                                      float (&acc)[2][8][4], int warp_m, int warp_n, int r,
                                      int c) {
#pragma unroll
    for (int kk = 0; kk < 2; kk++) {
        unsigned afr[2][4], bfr[8][2];
#pragma unroll
        for (int mt = 0; mt < 2; mt++) {
            int row0 = warp_m * 32 + mt * 16;
            afr[mt][0] = __float_as_uint(As[(row0 + r) * AS_STRIDE + kk * 8 + c]);
            afr[mt][1] = __float_as_uint(As[(row0 + 8 + r) * AS_STRIDE + kk * 8 + c]);
            afr[mt][2] = __float_as_uint(As[(row0 + r) * AS_STRIDE + kk * 8 + c + 4]);
            afr[mt][3] = __float_as_uint(As[(row0 + 8 + r) * AS_STRIDE + kk * 8 + c + 4]);
        }
#pragma unroll
        for (int nt = 0; nt < 8; nt++) {
            int col0 = warp_n * 64 + nt * 8;
            bfr[nt][0] = __float_as_uint(Bs[(kk * 8 + c) * BS_STRIDE + col0 + r]);
            bfr[nt][1] = __float_as_uint(Bs[(kk * 8 + c + 4) * BS_STRIDE + col0 + r]);
        }
#pragma unroll
        for (int mt = 0; mt < 2; mt++)
#pragma unroll
            for (int nt = 0; nt < 8; nt++) mma_tf32(acc[mt][nt], afr[mt], bfr[nt]);
    }
}

// ---------------- weight packing --------------------------------------------
// l*81920 + {U:0,V:16384,B:32768,C:49152,Ae:65536}; W0:163840(3x16384); Wk:212992(2x16384)
__global__ void pack_weights(const float* __restrict__ U, const float* __restrict__ V,
                             const float* __restrict__ B, const float* __restrict__ C,
                             const float* __restrict__ A, const float* __restrict__ W0,
                             const float* __restrict__ Wk) {
    int i = blockIdx.x * 256 + threadIdx.x;
    if (i >= 245760) return;
    int c = i >> 14, r = i & 16383;
    float v;
    if (c < 10) {
        int l = c / 5, w = c % 5;
        const float* base = (w == 0) ? U : (w == 1) ? V : (w == 2) ? B : (w == 3) ? C : A;
        v = base[l * 16384 + r];
    } else if (c < 13) {
        v = W0[(c - 10) * 16384 + r];
    } else {
        v = Wk[(c - 13) * 16384 + r];
    }
    g_wpack[i] = f2tf(v);
}

// ---------------- fold edge-embed into A0: WA = [emb_e_w; b] @ A0 ------------
__global__ void fold_WA(const float* __restrict__ ew, const float* __restrict__ ebias) {
    int c = threadIdx.x;  // 128
    const float* A = g_wpack + 65536;  // tf32-rounded A (layer 0)
    for (int f = 0; f < 8; f++) {
        float acc = 0.f;
        for (int k = 0; k < 128; k++) acc = fmaf(ew[f * 128 + k], A[k * 128 + c], acc);
        g_WA[f * 128 + c] = acc;
    }
    float acc = 0.f;
    for (int k = 0; k < 128; k++) acc = fmaf(ebias[k], A[k * 128 + c], acc);
    g_WA[8 * 128 + c] = acc;
}

// ---------------- node embedding (outputs tf32-rounded) ----------------------
template <int F, int ROWS>
__global__ void embed_kernel(const float* __restrict__ X, const float* __restrict__ W,
                             const float* __restrict__ b, float* __restrict__ out, int M) {
    __shared__ float ws[F * D];
    __shared__ float xs[ROWS][F];
    int tid = threadIdx.x;  // 128
    for (int i = tid; i < F * D; i += 128) ws[i] = W[i];
    float bias = b[tid];
    int r0 = blockIdx.x * ROWS;
    for (int i = tid; i < ROWS * F; i += 128) {
        int r = i / F, f = i % F;
        xs[r][f] = (r0 + r < M) ? X[(size_t)(r0 + r) * F + f] : 0.f;
    }
    __syncthreads();
    for (int r = 0; r < ROWS; r++) {
        if (r0 + r >= M) break;
        float acc = bias;
#pragma unroll
        for (int f = 0; f < F; f++) acc = fmaf(xs[r][f], ws[f * D + tid], acc);
        out[(size_t)(r0 + r) * D + tid] = f2tf(acc);
    }
}

// ---------------- plain TF32 GEMM: C[M,128]=A[M,128]@W -----------------------
struct SmemGemm {
    float As[2][128 * AS_STRIDE];
    float Bs[2][16 * BS_STRIDE];
};

__global__ __launch_bounds__(256) void gemm_tf32(const float* __restrict__ A,
                                                 const float* __restrict__ Wbase, int wstride,
                                                 float* __restrict__ Cbase, long cstride, int M) {
    __shared__ SmemGemm sm;
    const float* W = Wbase + (size_t)blockIdx.y * wstride;
    float* Cgm = Cbase + (size_t)blockIdx.y * cstride;
    int tid = threadIdx.x;
    int wid = tid >> 5, lane = tid & 31;
    int warp_m = wid & 3, warp_n = wid >> 2;
    int r = lane >> 2, c = lane & 3;
    int m0 = blockIdx.x * 128;

    float acc[2][8][4];
#pragma unroll
    for (int mt = 0; mt < 2; mt++)
#pragma unroll
        for (int nt = 0; nt < 8; nt++)
#pragma unroll
            for (int j = 0; j < 4; j++) acc[mt][nt][j] = 0.f;

    auto loadA = [&](int buf, int kt) {
#pragma unroll
        for (int i = 0; i < 2; i++) {
            int f = tid + i * 256;
            int row = f >> 2, k4 = f & 3;
            bool p = (m0 + row) < M;
            const float* g = A + (size_t)(m0 + row) * D + kt * 16 + k4 * 4;
            cpa16(&sm.As[buf][row * AS_STRIDE + k4 * 4], p ? g : (const void*)W, p);
        }
    };
    auto loadB = [&](int buf, int kt) {
#pragma unroll
        for (int i = 0; i < 2; i++) {
            int f = tid + i * 256;
            int k = f >> 5, n4 = f & 31;
            cpa16(&sm.Bs[buf][k * BS_STRIDE + n4 * 4], W + (size_t)(kt * 16 + k) * D + n4 * 4,
                  true);
        }
    };

    loadA(0, 0); loadB(0, 0); cpa_commit();
    loadA(1, 1); loadB(1, 1); cpa_commit();
    for (int kt = 0; kt < 8; kt++) {
        int buf = kt & 1;
        if (kt + 1 < 8) cpa_wait<1>(); else cpa_wait<0>();
        __syncthreads();
        do_kt(sm.As[buf], sm.Bs[buf], acc, warp_m, warp_n, r, c);
        __syncthreads();
        if (kt + 2 < 8) { loadA(buf, kt + 2); loadB(buf, kt + 2); cpa_commit(); }
    }

    int c2 = c * 2;
#pragma unroll
    for (int nt = 0; nt < 8; nt++) {
        int col = warp_n * 64 + nt * 8 + c2;
#pragma unroll
        for (int mt = 0; mt < 2; mt++) {
            int row = m0 + warp_m * 32 + mt * 16 + r;
            if (row < M)
                *reinterpret_cast<float2*>(Cgm + (size_t)row * D + col) =
                    make_float2(acc[mt][nt][0], acc[mt][nt][1]);
            if (row + 8 < M)
                *reinterpret_cast<float2*>(Cgm + (size_t)(row + 8) * D + col) =
                    make_float2(acc[mt][nt][2], acc[mt][nt][3]);
        }
    }
}

// ---- l=0 edge kernel (rank-9): stats over t2 = e_in@WA + WA[8] + hB[dst] +
//      hC[src] (t2 NOT materialized); gate e0 = f2tf(ebias + e_in@We);
//      fused scatter-max (single-path key atomics).
__global__ __launch_bounds__(256) void edge_l0_fused(const float* __restrict__ e_in,
                                                     const float* __restrict__ ew,
                                                     const float* __restrict__ ebias,
                                                     const int* __restrict__ src,
                                                     const int* __restrict__ dst) {
    __shared__ float s_ein[128 * 8];
    __shared__ int s_src[128];
    __shared__ int s_dst[128];
    __shared__ float red[4 * 256];
    int tid = threadIdx.x;
    int m0 = blockIdx.x * 128;
    if (tid < 128) {
        s_src[tid] = src[m0 + tid];
        s_dst[tid] = dst[m0 + tid];
    }
    for (int i = tid; i < 1024; i += 256) s_ein[i] = e_in[(size_t)m0 * 8 + i];

    int cp = tid & 63;   // column pair
    int c0 = cp * 2;
    int eg = tid >> 6;   // edge group 0..3
    float wa[9][2], we[8][2], eb2[2];
#pragma unroll
    for (int f = 0; f < 9; f++) {
        wa[f][0] = g_WA[f * 128 + c0];
        wa[f][1] = g_WA[f * 128 + c0 + 1];
    }
#pragma unroll
    for (int f = 0; f < 8; f++) {
        we[f][0] = ew[f * 128 + c0];
        we[f][1] = ew[f * 128 + c0 + 1];
    }
    eb2[0] = ebias[c0];
    eb2[1] = ebias[c0 + 1];
    __syncthreads();

    const float* hV = g_hUVBC + (size_t)NN * D;
    const float* hB = g_hUVBC + 2 * (size_t)NN * D;
    const float* hC = g_hUVBC + 3 * (size_t)NN * D;
    float sa = 0.f, qa = 0.f, sb = 0.f, qb = 0.f;
    for (int it = 0; it < 32; it++) {
        int row = it * 4 + eg;
        const float* er = s_ein + row * 8;
        float ta = wa[8][0], tb = wa[8][1];
        float ea = eb2[0], eb_ = eb2[1];
#pragma unroll
        for (int f = 0; f < 8; f++) {
            float x = er[f];
            ta = fmaf(x, wa[f][0], ta);
            tb = fmaf(x, wa[f][1], tb);
            ea = fmaf(x, we[f][0], ea);
            eb_ = fmaf(x, we[f][1], eb_);
        }
        ea = f2tf(ea);
        eb_ = f2tf(eb_);
        int s = s_src[row], d = s_dst[row];
        float2 hb = *reinterpret_cast<const float2*>(hB + (size_t)d * D + c0);
        float2 hc = *reinterpret_cast<const float2*>(hC + (size_t)s * D + c0);
        float2 hv = *reinterpret_cast<const float2*>(hV + (size_t)s * D + c0);
        float va = ta + hb.x + hc.x;
        float vb = tb + hb.y + hc.y;
        sa += va; qa += va * va;
        sb += vb; qb += vb * vb;
        float wga = 1.f / (1.f + __expf(-ea));
        float wgb = 1.f / (1.f + __expf(-eb_));
        atomicMax(&g_agg[(size_t)d * D + c0], fkey(hv.x * wga));
        atomicMax(&g_agg[(size_t)d * D + c0 + 1], fkey(hv.y * wgb));
    }
    red[tid] = sa;
    red[256 + tid] = qa;
    red[512 + tid] = sb;
    red[768 + tid] = qb;
    __syncthreads();
    if (tid < 64) {
        float S0 = red[tid] + red[tid + 64] + red[tid + 128] + red[tid + 192];
        float Q0 = red[256 + tid] + red[256 + tid + 64] + red[256 + tid + 128] + red[256 + tid + 192];
        float S1 = red[512 + tid] + red[512 + tid + 64] + red[512 + tid + 128] + red[512 + tid + 192];
        float Q1 = red[768 + tid] + red[768 + tid + 64] + red[768 + tid + 128] + red[768 + tid + 192];
        g_epsum[blockIdx.x * D + tid * 2] = S0;
        g_epsq[blockIdx.x * D + tid * 2] = Q0;
        g_epsum[blockIdx.x * D + tid * 2 + 1] = S1;
        g_epsq[blockIdx.x * D + tid * 2 + 1] = Q1;
    }
}

// ---- l=1 edge kernel: same block structure as l0; t2/e0 recomputed
//      bit-identically, BN-normalized with emean/erstd, gate + scatter-max.
//      No stats output (l=1 edge-side chain after scatter is dead).
__global__ __launch_bounds__(256) void edge_l1_fused(const float* __restrict__ e_in,
                                                     const float* __restrict__ ew,
                                                     const float* __restrict__ ebias,
                                                     const int* __restrict__ src,
                                                     const int* __restrict__ dst) {
    __shared__ float s_ein[128 * 8];
    __shared__ int s_src[128];
    __shared__ int s_dst[128];
    int tid = threadIdx.x;
    int m0 = blockIdx.x * 128;
    if (tid < 128) {
        s_src[tid] = src[m0 + tid];
        s_dst[tid] = dst[m0 + tid];
    }
    for (int i = tid; i < 1024; i += 256) s_ein[i] = e_in[(size_t)m0 * 8 + i];

    int cp = tid & 63;
    int c0 = cp * 2;
    int eg = tid >> 6;
    float wa[9][2], we[8][2], eb2[2], mn[2], rs[2];
#pragma unroll
    for (int f = 0; f < 9; f++) {
        wa[f][0] = g_WA[f * 128 + c0];
        wa[f][1] = g_WA[f * 128 + c0 + 1];
    }
#pragma unroll
    for (int f = 0; f < 8; f++) {
        we[f][0] = ew[f * 128 + c0];
        we[f][1] = ew[f * 128 + c0 + 1];
    }
    eb2[0] = ebias[c0];
    eb2[1] = ebias[c0 + 1];
    mn[0] = g_emean[c0];
    mn[1] = g_emean[c0 + 1];
    rs[0] = g_erstd[c0];
    rs[1] = g_erstd[c0 + 1];
    __syncthreads();

    const float* hV = g_hUVBC + (size_t)NN * D;
    const float* hB = g_hUVBC + 2 * (size_t)NN * D;
    const float* hC = g_hUVBC + 3 * (size_t)NN * D;
    for (int it = 0; it < 32; it++) {
        int row = it * 4 + eg;
        const float* er = s_ein + row * 8;
        float ta = wa[8][0], tb = wa[8][1];
        float ea = eb2[0], eb_ = eb2[1];
#pragma unroll
        for (int f = 0; f < 8; f++) {
            float x = er[f];
            ta = fmaf(x, wa[f][0], ta);
            tb = fmaf(x, wa[f][1], tb);
            ea = fmaf(x, we[f][0], ea);
            eb_ = fmaf(x, we[f][1], eb_);
        }
        ea = f2tf(ea);
        eb_ = f2tf(eb_);
        int s = s_src[row], d = s_dst[row];
        float2 hb = *reinterpret_cast<const float2*>(hB + (size_t)d * D + c0);
        float2 hc = *reinterpret_cast<const float2*>(hC + (size_t)s * D + c0);
        float2 hv = *reinterpret_cast<const float2*>(hV + (size_t)s * D + c0);
        float va = ta + hb.x + hc.x;
        float vb = tb + hb.y + hc.y;
        float xa = (va - mn[0]) * rs[0];
        float xb = (vb - mn[1]) * rs[1];
        float e1a = f2tf(ea + fmaxf(xa, 0.f));
        float e1b = f2tf(eb_ + fmaxf(xb, 0.f));
        float wga = 1.f / (1.f + __expf(-e1a));
        float wgb = 1.f / (1.f + __expf(-e1b));
        atomicMax(&g_agg[(size_t)d * D + c0], fkey(hv.x * wga));
        atomicMax(&g_agg[(size_t)d * D + c0 + 1], fkey(hv.y * wgb));
    }
}

// ---------------- fill agg with key(-inf) ------------------------------------
__global__ void fill_neginf_kernel() {
    int i = blockIdx.x * blockDim.x + threadIdx.x;
    uint4 v = make_uint4(KEY_NEGINF, KEY_NEGINF, KEY_NEGINF, KEY_NEGINF);
    if (i < NN * D / 4) reinterpret_cast<uint4*>(g_agg)[i] = v;
}

// ---------------- BN stats ---------------------------------------------------
__global__ void node_pre_stats() {
    int c = threadIdx.x;
    const float* hU = g_hUVBC;
    float s = 0.f, q = 0.f;
    for (int r = blockIdx.x; r < NN; r += gridDim.x) {
        float a = funkey(g_agg[(size_t)r * D + c]);
        if (!isfinite(a)) a = 0.f;
        float v = hU[(size_t)r * D + c] + a;
        s += v;
        q += v * v;
    }
    g_psum[blockIdx.x * D + c] = s;
    g_psq[blockIdx.x * D + c] = q;
}

__global__ void finalize_stats(const float* __restrict__ psum, const float* __restrict__ psq,
                               int nb, float inv_count, float* __restrict__ omean,
                               float* __restrict__ orstd) {
    int c = threadIdx.x;
    double s = 0.0, q = 0.0;
    for (int i = 0; i < nb; i++) {
        s += (double)psum[i * D + c];
        q += (double)psq[i * D + c];
    }
    double m = s * (double)inv_count;
    double v = q * (double)inv_count - m * m;
    omean[c] = (float)m;
    orstd[c] = rsqrtf((float)v + 1e-5f);
}

__global__ void node_update(const float* __restrict__ h, float* __restrict__ hn) {
    int i = blockIdx.x * blockDim.x + threadIdx.x;
    if (i >= NN * D) return;
    int c = i & 127;
    const float* hU = g_hUVBC;
    float a = funkey(g_agg[i]);
    if (!isfinite(a)) a = 0.f;
    float v = hU[i] + a;
    float x = (v - g_mean[c]) * g_rstd[c];
    hn[i] = f2tf(h[i] + fmaxf(x, 0.f));
}

// ---------------- moy + vmoy -------------------------------------------------
__global__ void moy_partial(const float* __restrict__ h) {
    int c = threadIdx.x;
    float s = 0.f;
    for (int r = blockIdx.x; r < NN; r += gridDim.x) s += h[(size_t)r * D + c];
    g_psum[blockIdx.x * D + c] = s;
}

__global__ void finalize_moy_vmoy(const float* __restrict__ W0_b) {
    __shared__ float moy_s[D];
    int c = threadIdx.x;
    double s = 0.0;
    for (int i = 0; i < NBS; i++) s += (double)g_psum[i * D + c];
    moy_s[c] = (float)(s / (double)NN);
    __syncthreads();
    float v = W0_b[c];
    const float* W0a = g_wpack + 163840;
#pragma unroll 4
    for (int k = 0; k < D; k++) v = fmaf(moy_s[k], W0a[k * D + c], v);
    g_vmoy[c] = v;
}

// ---------------- fused readout MLP ------------------------------------------
template <bool ROUND>
__device__ __forceinline__ void mlp_stage(float* __restrict__ X, float* __restrict__ Wb,
                                          const float* __restrict__ Wg,
                                          const float* __restrict__ bias, int tid, int warp_m,
                                          int warp_n, int r, int c) {
    float acc[2][8][4];
#pragma unroll
    for (int mt = 0; mt < 2; mt++)
#pragma unroll
        for (int nt = 0; nt < 8; nt++)
#pragma unroll
            for (int j = 0; j < 4; j++) acc[mt][nt][j] = 0.f;

    auto loadW = [&](int buf, int kt) {
#pragma unroll
        for (int i = 0; i < 2; i++) {
            int f = tid + i * 256;
            int k = f >> 5, n4 = f & 31;
            cpa16(&Wb[buf * (16 * BS_STRIDE) + k * BS_STRIDE + n4 * 4],
                  Wg + (size_t)(kt * 16 + k) * D + n4 * 4, true);
        }
    };
    loadW(0, 0); cpa_commit();
    loadW(1, 1); cpa_commit();
    for (int kt = 0; kt < 8; kt++) {
        int buf = kt & 1;
        if (kt + 1 < 8) cpa_wait<1>(); else cpa_wait<0>();
        __syncthreads();
        do_kt(X + kt * (128 * AS_STRIDE), Wb + buf * (16 * BS_STRIDE), acc, warp_m, warp_n, r, c);
        __syncthreads();
        if (kt + 2 < 8) { loadW(buf, kt + 2); cpa_commit(); }
    }
    int c2 = c * 2;
#pragma unroll
    for (int nt = 0; nt < 8; nt++) {
        int col = warp_n * 64 + nt * 8 + c2;
        float b0 = bias[col], b1 = bias[col + 1];
#pragma unroll
        for (int mt = 0; mt < 2; mt++) {
            int row = warp_m * 32 + mt * 16 + r;
            float v0 = fmaxf(acc[mt][nt][0] + b0, 0.f);
            float v1 = fmaxf(acc[mt][nt][1] + b1, 0.f);
            float v2 = fmaxf(acc[mt][nt][2] + b0, 0.f);
            float v3 = fmaxf(acc[mt][nt][3] + b1, 0.f);
            if (ROUND) { v0 = f2tf(v0); v1 = f2tf(v1); v2 = f2tf(v2); v3 = f2tf(v3); }
            X[(col >> 4) * (128 * AS_STRIDE) + row * AS_STRIDE + (col & 15)] = v0;
            X[(col >> 4) * (128 * AS_STRIDE) + (row + 8) * AS_STRIDE + (col & 15)] = v2;
            X[((col + 1) >> 4) * (128 * AS_STRIDE) + row * AS_STRIDE + ((col + 1) & 15)] = v1;
            X[((col + 1) >> 4) * (128 * AS_STRIDE) + (row + 8) * AS_STRIDE + ((col + 1) & 15)] = v3;
        }
    }
    __syncthreads();
}

__global__ __launch_bounds__(256) void readout_fused(const int* __restrict__ src,
                                                     const int* __restrict__ dst,
                                                     const float* __restrict__ Wk,
                                                     const float* __restrict__ Wk_b,
                                                     const float* __restrict__ wf,
                                                     const float* __restrict__ wfb,
                                                     float* __restrict__ out) {
    extern __shared__ float dyn[];
    float* X = dyn;                       // 8*128*20 = 20480
    float* Wb = dyn + 20480;              // 2*16*136 = 4352
    float* vmoy_s = Wb + 4352;            // 128
    float* wf_s = vmoy_s + 128;           // 128
    int* s_src = (int*)(wf_s + 128);      // 128
    int* s_dst = s_src + 128;             // 128
    int tid = threadIdx.x;
    int m0 = blockIdx.x * 128;
    if (tid < 128) {
        s_src[tid] = src[m0 + tid];
        s_dst[tid] = dst[m0 + tid];
        vmoy_s[tid] = g_vmoy[tid];
        wf_s[tid] = wf[tid];
    }
    __syncthreads();
    const float* P = g_hUVBC;
    const float* Q = g_hUVBC + (size_t)NN * D;
    {
        int row = tid >> 1, half = tid & 1;
        const float* p = P + (size_t)s_src[row] * D + half * 64;
        const float* q = Q + (size_t)s_dst[row] * D + half * 64;
#pragma unroll
        for (int i = 0; i < 16; i++) {
            int colb = half * 64 + i * 4;
            float4 pv = *reinterpret_cast<const float4*>(p + i * 4);
            float4 qv = *reinterpret_cast<const float4*>(q + i * 4);
            float4 mv = *reinterpret_cast<const float4*>(vmoy_s + colb);
            float4 v;
            v.x = f2tf(fmaxf(pv.x + qv.x + mv.x, 0.f));
            v.y = f2tf(fmaxf(pv.y + qv.y + mv.y, 0.f));
            v.z = f2tf(fmaxf(pv.z + qv.z + mv.z, 0.f));
            v.w = f2tf(fmaxf(pv.w + qv.w + mv.w, 0.f));
            *reinterpret_cast<float4*>(X + (colb >> 4) * (128 * AS_STRIDE) + row * AS_STRIDE +
                                       (colb & 15)) = v;
        }
    }
    __syncthreads();
    int wid = tid >> 5, lane = tid & 31;
    int warp_m = wid & 3, warp_n = wid >> 2;
    int r = lane >> 2, c = lane & 3;
    mlp_stage<true>(X, Wb, Wk, Wk_b, tid, warp_m, warp_n, r, c);
    mlp_stage<false>(X, Wb, Wk + 16384, Wk_b + 128, tid, warp_m, warp_n, r, c);
    if (tid < 128) {
        float s = 0.f;
#pragma unroll
        for (int kt = 0; kt < 8; kt++)
#pragma unroll
            for (int k = 0; k < 16; k++)
                s = fmaf(X[kt * (128 * AS_STRIDE) + tid * AS_STRIDE + k], wf_s[kt * 16 + k], s);
        out[m0 + tid] = 1.f / (1.f + expf(-(s + wfb[0])));
    }
}

// ---------------- host -------------------------------------------------------
extern "C" void kernel_launch(void* const* d_in, const int* in_sizes, int n_in,
                              void* d_out, int out_size) {
    const float* h_in = (const float*)d_in[0];
    const float* e_in = (const float*)d_in[1];
    const float* emb_n_w = (const float*)d_in[2];
    const float* emb_n_b = (const float*)d_in[3];
    const float* emb_e_w = (const float*)d_in[4];
    const float* emb_e_b = (const float*)d_in[5];
    const float* Uw = (const float*)d_in[6];
    const float* Vw = (const float*)d_in[7];
    const float* Aw = (const float*)d_in[8];
    const float* Bw = (const float*)d_in[9];
    const float* Cw = (const float*)d_in[10];
    const float* W0_w = (const float*)d_in[11];
    const float* W0_b = (const float*)d_in[12];
    const float* Wk_w = (const float*)d_in[13];
    const float* Wk_b = (const float*)d_in[14];
    const float* Wf_w = (const float*)d_in[15];
    const float* Wf_b = (const float*)d_in[16];
    const int* src = (const int*)d_in[17];
    const int* dst = (const int*)d_in[18];
    float* out = (float*)d_out;

    float *h0, *h1, *huvbc, *wpack, *psum, *psq, *epsum, *epsq, *gmean, *grstd, *gemean, *gerstd;
    cudaGetSymbolAddress((void**)&h0, g_h0);
    cudaGetSymbolAddress((void**)&h1, g_h1);
    cudaGetSymbolAddress((void**)&huvbc, g_hUVBC);
    cudaGetSymbolAddress((void**)&wpack, g_wpack);
    cudaGetSymbolAddress((void**)&psum, g_psum);
    cudaGetSymbolAddress((void**)&psq, g_psq);
    cudaGetSymbolAddress((void**)&epsum, g_epsum);
    cudaGetSymbolAddress((void**)&epsq, g_epsq);
    cudaGetSymbolAddress((void**)&gmean, g_mean);
    cudaGetSymbolAddress((void**)&grstd, g_rstd);
    cudaGetSymbolAddress((void**)&gemean, g_emean);
    cudaGetSymbolAddress((void**)&gerstd, g_erstd);

    cudaFuncSetAttribute(readout_fused, cudaFuncAttributeMaxDynamicSharedMemorySize, 103424);

    const int GN = (NN + 127) / 128;  // 391

    pack_weights<<<960, 256>>>(Uw, Vw, Bw, Cw, Aw, W0_w, Wk_w);
    fold_WA<<<1, 128>>>(emb_e_w, emb_e_b);
    embed_kernel<16, 8><<<(NN + 7) / 8, 128>>>(h_in, emb_n_w, emb_n_b, h0, NN);

    // ---- layer 0 ----
    fill_neginf_kernel<<<(NN * D / 4 + 255) / 256, 256>>>();
    gemm_tf32<<<dim3(GN, 4), 256>>>(h0, wpack, 16384, huvbc, (long)NN * D, NN);
    edge_l0_fused<<<GEB, 256>>>(e_in, emb_e_w, emb_e_b, src, dst);
    finalize_stats<<<1, 128>>>(epsum, epsq, GEB, 1.f / (float)NE, gemean, gerstd);
    node_pre_stats<<<NBS, 128>>>();
    finalize_stats<<<1, 128>>>(psum, psq, NBS, 1.f / (float)NN, gmean, grstd);
    node_update<<<(NN * D + 255) / 256, 256>>>(h0, h1);

    // ---- layer 1 ----
    fill_neginf_kernel<<<(NN * D / 4 + 255) / 256, 256>>>();
    gemm_tf32<<<dim3(GN, 2), 256>>>(h1, wpack + 81920, 16384, huvbc, (long)NN * D, NN);
    edge_l1_fused<<<GEB, 256>>>(e_in, emb_e_w, emb_e_b, src, dst);
    node_pre_stats<<<NBS, 128>>>();
    finalize_stats<<<1, 128>>>(psum, psq, NBS, 1.f / (float)NN, gmean, grstd);
    node_update<<<(NN * D + 255) / 256, 256>>>(h1, h0);

    // ---- readout (final h is in h0) ----
    moy_partial<<<NBS, 128>>>(h0);
    finalize_moy_vmoy<<<1, 128>>>(W0_b);
    gemm_tf32<<<dim3(GN, 2), 256>>>(h0, wpack + 163840 + 16384, 16384, huvbc, (long)NN * D, NN);
    readout_fused<<<GEB, 256, 103424>>>(src, dst, wpack + 212992, Wk_b, Wf_w, Wf_b, out);
}